// round 8
// baseline (speedup 1.0000x reference)
#include <cuda_runtime.h>
#include <cuda_bf16.h>
#include <cstdint>

// Problem constants
#define BB 4
#define TT 512
#define EE 1024
#define HH 16
#define DK 64
#define BT (BB*TT)          // 2048

// ---------------------------------------------------------------------------
// Device scratch
// ---------------------------------------------------------------------------
__device__ float g_qh[BB*HH*TT*DK];          // head-major qlin
__device__ float g_vh[BB*HH*TT*DK];          // head-major vlin
__device__ __nv_bfloat16 g_xhi[BT*EE], g_xlo[BT*EE];    // x split
__device__ __nv_bfloat16 g_ahi[BT*EE], g_alo[BT*EE];    // attn split
__device__ __nv_bfloat16 g_wt_hi[3][EE*EE];  // W^T splits: [n][k]  0=Wq 1=Wv 2=Wo
__device__ __nv_bfloat16 g_wt_lo[3][EE*EE];

__device__ __forceinline__ uint32_t smem_u32(const void* p) {
    uint32_t a;
    asm("{ .reg .u64 t; cvta.to.shared.u64 t, %1; cvt.u32.u64 %0, t; }"
        : "=r"(a) : "l"(p));
    return a;
}

__device__ __forceinline__ void cp16(uint32_t dst, const void* src) {
    asm volatile("cp.async.cg.shared.global [%0], [%1], 16;"
                 :: "r"(dst), "l"(src) : "memory");
}

#define LDSM_X4(r0,r1,r2,r3,addr) \
    asm volatile("ldmatrix.sync.aligned.m8n8.x4.shared.b16 {%0,%1,%2,%3}, [%4];" \
                 : "=r"(r0), "=r"(r1), "=r"(r2), "=r"(r3) : "r"(addr))
#define MMA_BF16(c, a, b) \
    asm volatile("mma.sync.aligned.m16n8k16.row.col.f32.bf16.bf16.f32 " \
                 "{%0,%1,%2,%3}, {%4,%5,%6,%7}, {%8,%9}, {%0,%1,%2,%3};" \
                 : "+f"((c)[0]), "+f"((c)[1]), "+f"((c)[2]), "+f"((c)[3]) \
                 : "r"((a)[0]), "r"((a)[1]), "r"((a)[2]), "r"((a)[3]), \
                   "r"((b)[0]), "r"((b)[1]))

// smem: 4 tiles of 128 rows x 80 B, 2-stage pipeline -> 80 KB -> 2 CTA/SM
#define ROWP   80
#define TILEB  (128*ROWP)            // 10240
#define OFF_AH 0
#define OFF_AL (1*TILEB)
#define OFF_BH (2*TILEB)
#define OFF_BL (3*TILEB)
#define BUFB   (4*TILEB)             // 40960
#define NSTAGE 2
#define SMEM_BYTES (NSTAGE*BUFB)     // 81920

#define NKT 32                       // 32 K-tiles of 32 -> K = 1024

// ---------------------------------------------------------------------------
// Split fp32 x -> bf16 hi/lo
// ---------------------------------------------------------------------------
__global__ __launch_bounds__(256) void split_src(const float* __restrict__ src)
{
    int i = (blockIdx.x * 256 + threadIdx.x) * 4;
    float4 v = *(const float4*)(src + i);
    __nv_bfloat16 h[4], l[4];
    h[0] = __float2bfloat16(v.x); l[0] = __float2bfloat16(v.x - __bfloat162float(h[0]));
    h[1] = __float2bfloat16(v.y); l[1] = __float2bfloat16(v.y - __bfloat162float(h[1]));
    h[2] = __float2bfloat16(v.z); l[2] = __float2bfloat16(v.z - __bfloat162float(h[2]));
    h[3] = __float2bfloat16(v.w); l[3] = __float2bfloat16(v.w - __bfloat162float(h[3]));
    *(uint2*)(g_xhi + i) = *(uint2*)h;
    *(uint2*)(g_xlo + i) = *(uint2*)l;
}

// ---------------------------------------------------------------------------
// Transpose + split weights: g_wt[z][n][k] = split(W_z[k][n])
// ---------------------------------------------------------------------------
__global__ void split_w(const float* __restrict__ Wq, const float* __restrict__ Wv,
                        const float* __restrict__ Wo)
{
    __shared__ float tile[32][33];
    const int z = blockIdx.z;
    const float* W = z == 0 ? Wq : (z == 1 ? Wv : Wo);
    const int n0 = blockIdx.x * 32;
    const int k0 = blockIdx.y * 32;
    const int tx = threadIdx.x, ty = threadIdx.y;

    #pragma unroll
    for (int i = 0; i < 4; i++)
        tile[ty + 8*i][tx] = W[(size_t)(k0 + ty + 8*i)*EE + n0 + tx];
    __syncthreads();
    #pragma unroll
    for (int i = 0; i < 4; i++) {
        int r = ty + 8*i;
        float v = tile[tx][r];
        __nv_bfloat16 h = __float2bfloat16(v);
        __nv_bfloat16 l = __float2bfloat16(v - __bfloat162float(h));
        size_t o = (size_t)(n0 + r)*EE + k0 + tx;
        g_wt_hi[z][o] = h;
        g_wt_lo[z][o] = l;
    }
}

// ---------------------------------------------------------------------------
// Split-bf16 tensor-core GEMM via mma.sync.
// CTA 128x128, KT=32, 8 warps (2m x 4n), 2-stage single-sync pipeline.
// Hazard-free ordering: wait -> bar -> issue next load -> compute.
// ---------------------------------------------------------------------------
__global__ __launch_bounds__(256, 2) void mma_gemm(
    int wbase, const float* __restrict__ bias0, const float* __restrict__ bias1,
    float* __restrict__ outp, int mode)
{
    extern __shared__ char smem[];
    const uint32_t sb = smem_u32(smem);
    const int tid = threadIdx.x;
    const int wid = tid >> 5;
    const int l   = tid & 31;
    const int wm  = wid & 1;
    const int wn  = wid >> 1;

    const int n0 = blockIdx.x * 128;
    const int m0 = blockIdx.y * 128;
    const int z  = blockIdx.z;
    const float* bias = z ? bias1 : bias0;

    const __nv_bfloat16* Ah = mode ? g_ahi : g_xhi;
    const __nv_bfloat16* Al = mode ? g_alo : g_xlo;
    const __nv_bfloat16* Bh = g_wt_hi[wbase + z];
    const __nv_bfloat16* Bl = g_wt_lo[wbase + z];

    const int gr  = tid >> 1;
    const int gs  = tid & 1;
    const size_t aoff = (size_t)(m0 + gr) * EE + gs * 16;
    const size_t boff = (size_t)(n0 + gr) * EE + gs * 16;
    const uint32_t srow = gr * ROWP + gs * 32;

    float acc[4][4][4] = {};

    auto load_tile = [&](int kt, int b) {
        const int kc = kt * 32;
        const uint32_t d = sb + b * BUFB + srow;
        cp16(d + OFF_AH,      Ah + aoff + kc);
        cp16(d + OFF_AH + 16, Ah + aoff + kc + 8);
        cp16(d + OFF_AL,      Al + aoff + kc);
        cp16(d + OFF_AL + 16, Al + aoff + kc + 8);
        cp16(d + OFF_BH,      Bh + boff + kc);
        cp16(d + OFF_BH + 16, Bh + boff + kc + 8);
        cp16(d + OFF_BL,      Bl + boff + kc);
        cp16(d + OFF_BL + 16, Bl + boff + kc + 8);
        asm volatile("cp.async.commit_group;" ::: "memory");
    };

    const uint32_t aBase  = (uint32_t)((wm*64 + (l & 15)) * ROWP + (l & 16));
    const uint32_t bBase4 = (uint32_t)((wn*32 + (l & 7) + ((l & 16) >> 1)) * ROWP
                                       + ((l & 8) << 1));

    load_tile(0, 0);

    for (int kt = 0; kt < NKT; kt++) {
        // tile kt arrived (it's the only outstanding group at this point)
        asm volatile("cp.async.wait_group 0;" ::: "memory");
        // all threads: prev compute done (frees buffer (kt+1)&1) + tile kt visible
        __syncthreads();
        if (kt + 1 < NKT) load_tile(kt + 1, (kt + 1) & 1);

        const uint32_t bufb = sb + (kt & 1) * BUFB;
        #pragma unroll
        for (int ks = 0; ks < 2; ks++) {
            const uint32_t kb = ks * 32;
            uint32_t bh[4][2], ah[4][4], al[4][4];
            LDSM_X4(bh[0][0], bh[0][1], bh[1][0], bh[1][1],
                    bufb + OFF_BH + bBase4 + kb);
            LDSM_X4(bh[2][0], bh[2][1], bh[3][0], bh[3][1],
                    bufb + OFF_BH + bBase4 + 16*ROWP + kb);
            #pragma unroll
            for (int mf = 0; mf < 4; mf++)
                LDSM_X4(ah[mf][0], ah[mf][1], ah[mf][2], ah[mf][3],
                        bufb + OFF_AH + aBase + mf*16*ROWP + kb);
            #pragma unroll
            for (int mf = 0; mf < 4; mf++)
                #pragma unroll
                for (int nf = 0; nf < 4; nf++)
                    MMA_BF16(acc[mf][nf], ah[mf], bh[nf]);
            #pragma unroll
            for (int mf = 0; mf < 4; mf++)
                LDSM_X4(al[mf][0], al[mf][1], al[mf][2], al[mf][3],
                        bufb + OFF_AL + aBase + mf*16*ROWP + kb);
            #pragma unroll
            for (int mf = 0; mf < 4; mf++)
                #pragma unroll
                for (int nf = 0; nf < 4; nf++)
                    MMA_BF16(acc[mf][nf], al[mf], bh[nf]);
            LDSM_X4(bh[0][0], bh[0][1], bh[1][0], bh[1][1],
                    bufb + OFF_BL + bBase4 + kb);
            LDSM_X4(bh[2][0], bh[2][1], bh[3][0], bh[3][1],
                    bufb + OFF_BL + bBase4 + 16*ROWP + kb);
            #pragma unroll
            for (int mf = 0; mf < 4; mf++)
                #pragma unroll
                for (int nf = 0; nf < 4; nf++)
                    MMA_BF16(acc[mf][nf], ah[mf], bh[nf]);
        }
    }

    // Epilogue
    const int g   = l >> 2;
    const int tig = l & 3;
    #pragma unroll
    for (int mf = 0; mf < 4; mf++) {
        const int m = m0 + wm*64 + mf*16 + g;
        const int b = m >> 9;
        const int t = m & 511;
        #pragma unroll
        for (int nf = 0; nf < 4; nf++) {
            const int n = n0 + wn*32 + nf*8 + tig*2;
            float v0 = acc[mf][nf][0] + bias[n];
            float v1 = acc[mf][nf][1] + bias[n+1];
            float v2 = acc[mf][nf][2] + bias[n];
            float v3 = acc[mf][nf][3] + bias[n+1];
            if (mode == 0) {
                float* dst = z ? g_vh : g_qh;
                int h0 = n & (HH-1),   d0 = n >> 4;
                int h1 = (n+1)&(HH-1), d1 = (n+1) >> 4;
                dst[((b*HH + h0)*TT + t)*DK + d0]     = v0;
                dst[((b*HH + h1)*TT + t)*DK + d1]     = v1;
                dst[((b*HH + h0)*TT + t + 8)*DK + d0] = v2;
                dst[((b*HH + h1)*TT + t + 8)*DK + d1] = v3;
            } else {
                outp[(size_t)m*EE + n]       = v0;
                outp[(size_t)m*EE + n + 1]   = v1;
                outp[(size_t)(m+8)*EE + n]   = v2;
                outp[(size_t)(m+8)*EE + n+1] = v3;
            }
        }
    }
}

// ---------------------------------------------------------------------------
// Windowed attention, conflict-free V phase, fused bf16 split epilogue.
// grid (16, 64), 256 threads
// ---------------------------------------------------------------------------
__global__ __launch_bounds__(256) void attn_kernel()
{
    __shared__ float Ks[96][68];
    __shared__ float Ps[32][68];

    const int bh = blockIdx.y;
    const int t0 = blockIdx.x * 32;
    const float* qb = g_qh + bh*TT*DK;
    const float* vb = g_vh + bh*TT*DK;

    for (int idx = threadIdx.x; idx < 96*16; idx += 256) {
        int r  = idx >> 4;
        int c4 = (idx & 15) << 2;
        int src = t0 - 32 + r;
        src = src < 0 ? 0 : (src > TT-1 ? TT-1 : src);
        *(float4*)&Ks[r][c4] = *(const float4*)(qb + src*DK + c4);
    }
    __syncthreads();

    const int t_l = threadIdx.x >> 3;
    const int wg  = threadIdx.x & 7;
    const float scale = 1.0f / 32.0f;

    float q[64];
    const int qrow = 32 + t_l;
    #pragma unroll
    for (int i = 0; i < 16; i++) {
        float4 v = *(const float4*)&Ks[qrow][4*i];
        q[4*i] = v.x; q[4*i+1] = v.y; q[4*i+2] = v.z; q[4*i+3] = v.w;
    }

    float acc[8];
    #pragma unroll
    for (int j = 0; j < 8; j++) {
        const int r = t_l + wg + 8*j;
        float a = 0.f;
        #pragma unroll
        for (int i = 0; i < 16; i++) {
            float4 kv = *(const float4*)&Ks[r][4*i];
            a = fmaf(q[4*i],   kv.x, a);
            a = fmaf(q[4*i+1], kv.y, a);
            a = fmaf(q[4*i+2], kv.z, a);
            a = fmaf(q[4*i+3], kv.w, a);
        }
        acc[j] = a;
    }

    float m = -1e30f;
    #pragma unroll
    for (int j = 0; j < 8; j++) { acc[j] *= scale; m = fmaxf(m, acc[j]); }
    #pragma unroll
    for (int off = 1; off < 8; off <<= 1)
        m = fmaxf(m, __shfl_xor_sync(0xffffffffu, m, off));
    float s = 0.f, p[8];
    #pragma unroll
    for (int j = 0; j < 8; j++) { p[j] = __expf(acc[j] - m); s += p[j]; }
    #pragma unroll
    for (int off = 1; off < 8; off <<= 1)
        s += __shfl_xor_sync(0xffffffffu, s, off);
    float inv = 1.0f / s;
    #pragma unroll
    for (int j = 0; j < 8; j++)
        Ps[t_l][wg + 8*j] = p[j] * inv;

    __syncthreads();

    for (int idx = threadIdx.x; idx < 96*16; idx += 256) {
        int r  = idx >> 4;
        int c4 = (idx & 15) << 2;
        int src = t0 - 32 + r;
        src = src < 0 ? 0 : (src > TT-1 ? TT-1 : src);
        *(float4*)&Ks[r][c4] = *(const float4*)(vb + src*DK + c4);
    }
    __syncthreads();

    const int dg = wg;
    float ao[8] = {};
    #pragma unroll 8
    for (int w = 0; w < 64; w++) {
        float pw = Ps[t_l][w];
        const int r = t_l + w;
        float4 v0 = *(const float4*)&Ks[r][dg*4];
        float4 v1 = *(const float4*)&Ks[r][32 + dg*4];
        ao[0] = fmaf(pw, v0.x, ao[0]); ao[1] = fmaf(pw, v0.y, ao[1]);
        ao[2] = fmaf(pw, v0.z, ao[2]); ao[3] = fmaf(pw, v0.w, ao[3]);
        ao[4] = fmaf(pw, v1.x, ao[4]); ao[5] = fmaf(pw, v1.y, ao[5]);
        ao[6] = fmaf(pw, v1.z, ao[6]); ao[7] = fmaf(pw, v1.w, ao[7]);
    }

    const int b = bh >> 4, h = bh & 15;
    const int t = t0 + t_l;
    const int base = (b*TT + t)*EE + h*DK;
    __nv_bfloat16 hh[8], ll[8];
    #pragma unroll
    for (int i = 0; i < 8; i++) {
        hh[i] = __float2bfloat16(ao[i]);
        ll[i] = __float2bfloat16(ao[i] - __bfloat162float(hh[i]));
    }
    *(uint2*)(g_ahi + base + dg*4)      = *(uint2*)(hh);
    *(uint2*)(g_ahi + base + 32 + dg*4) = *(uint2*)(hh + 4);
    *(uint2*)(g_alo + base + dg*4)      = *(uint2*)(ll);
    *(uint2*)(g_alo + base + 32 + dg*4) = *(uint2*)(ll + 4);
}

// ---------------------------------------------------------------------------
// Inputs: 0:x 1:position_mask(unused) 2:Wq 3:bq 4:Wv 5:bv 6:Wo 7:bo
// ---------------------------------------------------------------------------
extern "C" void kernel_launch(void* const* d_in, const int* in_sizes, int n_in,
                              void* d_out, int out_size)
{
    const float* x  = (const float*)d_in[0];
    const float* Wq = (const float*)d_in[2];
    const float* bq = (const float*)d_in[3];
    const float* Wv = (const float*)d_in[4];
    const float* bv = (const float*)d_in[5];
    const float* Wo = (const float*)d_in[6];
    const float* bo = (const float*)d_in[7];
    float* out = (float*)d_out;

    cudaFuncSetAttribute(mma_gemm, cudaFuncAttributeMaxDynamicSharedMemorySize, SMEM_BYTES);

    split_src<<<BT*EE/1024, 256>>>(x);
    split_w<<<dim3(32, 32, 3), dim3(32, 8)>>>(Wq, Wv, Wo);
    mma_gemm<<<dim3(8, 16, 2), 256, SMEM_BYTES>>>(0, bq, bv, nullptr, 0);
    attn_kernel<<<dim3(16, 64), 256>>>();
    mma_gemm<<<dim3(8, 16, 1), 256, SMEM_BYTES>>>(2, bo, bo, out, 1);
}

// round 9
// speedup vs baseline: 1.2600x; 1.2600x over previous
#include <cuda_runtime.h>
#include <cuda_fp16.h>
#include <cstdint>

// Problem constants
#define BB 4
#define TT 512
#define EE 1024
#define HH 16
#define DK 64
#define BT (BB*TT)          // 2048

// ---------------------------------------------------------------------------
// Device scratch
// ---------------------------------------------------------------------------
__device__ float g_qh[BB*HH*TT*DK];          // head-major qlin
__device__ float g_vh[BB*HH*TT*DK];          // head-major vlin
__device__ __half g_xhi[BT*EE], g_xlo[BT*EE];    // x split (fp16 hi/lo)
__device__ __half g_ahi[BT*EE], g_alo[BT*EE];    // attn split
__device__ __half g_w16[3][EE*EE];           // W^T fp16: [n][k]  0=Wq 1=Wv 2=Wo

__device__ __forceinline__ uint32_t smem_u32(const void* p) {
    uint32_t a;
    asm("{ .reg .u64 t; cvta.to.shared.u64 t, %1; cvt.u32.u64 %0, t; }"
        : "=r"(a) : "l"(p));
    return a;
}

__device__ __forceinline__ void cp16(uint32_t dst, const void* src) {
    asm volatile("cp.async.cg.shared.global [%0], [%1], 16;"
                 :: "r"(dst), "l"(src) : "memory");
}

#define LDSM_X4(r0,r1,r2,r3,addr) \
    asm volatile("ldmatrix.sync.aligned.m8n8.x4.shared.b16 {%0,%1,%2,%3}, [%4];" \
                 : "=r"(r0), "=r"(r1), "=r"(r2), "=r"(r3) : "r"(addr))
#define MMA_F16(c, a, b) \
    asm volatile("mma.sync.aligned.m16n8k16.row.col.f32.f16.f16.f32 " \
                 "{%0,%1,%2,%3}, {%4,%5,%6,%7}, {%8,%9}, {%0,%1,%2,%3};" \
                 : "+f"((c)[0]), "+f"((c)[1]), "+f"((c)[2]), "+f"((c)[3]) \
                 : "r"((a)[0]), "r"((a)[1]), "r"((a)[2]), "r"((a)[3]), \
                   "r"((b)[0]), "r"((b)[1]))

// smem: 3 tiles of 128 rows x 80 B (AH, AL, B), 2-stage
#define ROWP   80
#define TILEB  (128*ROWP)            // 10240
#define OFF_AH 0
#define OFF_AL (1*TILEB)
#define OFF_B  (2*TILEB)
#define BUFB   (3*TILEB)             // 30720
#define SMEM_BYTES (2*BUFB)          // 61440

#define NKT 32                       // 32 K-tiles of 32 -> K = 1024

// ---------------------------------------------------------------------------
// Split fp32 x -> fp16 hi/lo
// ---------------------------------------------------------------------------
__global__ __launch_bounds__(256) void split_src(const float* __restrict__ src)
{
    int i = (blockIdx.x * 256 + threadIdx.x) * 4;
    float4 v = *(const float4*)(src + i);
    __half h[4], l[4];
    h[0] = __float2half(v.x); l[0] = __float2half(v.x - __half2float(h[0]));
    h[1] = __float2half(v.y); l[1] = __float2half(v.y - __half2float(h[1]));
    h[2] = __float2half(v.z); l[2] = __float2half(v.z - __half2float(h[2]));
    h[3] = __float2half(v.w); l[3] = __float2half(v.w - __half2float(h[3]));
    *(uint2*)(g_xhi + i) = *(uint2*)h;
    *(uint2*)(g_xlo + i) = *(uint2*)l;
}

// ---------------------------------------------------------------------------
// Transpose weights to fp16: g_w16[z][n][k] = fp16(W_z[k][n])
// grid (32, 32, 3), block (32, 8)
// ---------------------------------------------------------------------------
__global__ void split_w(const float* __restrict__ Wq, const float* __restrict__ Wv,
                        const float* __restrict__ Wo)
{
    __shared__ float tile[32][33];
    const int z = blockIdx.z;
    const float* W = z == 0 ? Wq : (z == 1 ? Wv : Wo);
    const int n0 = blockIdx.x * 32;
    const int k0 = blockIdx.y * 32;
    const int tx = threadIdx.x, ty = threadIdx.y;

    #pragma unroll
    for (int i = 0; i < 4; i++)
        tile[ty + 8*i][tx] = W[(size_t)(k0 + ty + 8*i)*EE + n0 + tx];
    __syncthreads();
    #pragma unroll
    for (int i = 0; i < 4; i++) {
        int r = ty + 8*i;
        g_w16[z][(size_t)(n0 + r)*EE + k0 + tx] = __float2half(tile[tx][r]);
    }
}

// ---------------------------------------------------------------------------
// 2-pass split-fp16 tensor-core GEMM via mma.sync.
// C[m,n] = sum_k (Ah+Al)[m,k]*fp16(W)[k,n] + bias[n]
// CTA 128x128, KT=32, 8 warps (2m x 4n), 2-stage single-sync pipeline.
// ---------------------------------------------------------------------------
__global__ __launch_bounds__(256, 2) void mma_gemm(
    int wbase, const float* __restrict__ bias0, const float* __restrict__ bias1,
    float* __restrict__ outp, int mode)
{
    extern __shared__ char smem[];
    const uint32_t sb = smem_u32(smem);
    const int tid = threadIdx.x;
    const int wid = tid >> 5;
    const int l   = tid & 31;
    const int wm  = wid & 1;
    const int wn  = wid >> 1;

    const int n0 = blockIdx.x * 128;
    const int m0 = blockIdx.y * 128;
    const int z  = blockIdx.z;
    const float* bias = z ? bias1 : bias0;

    const __half* Ah = mode ? g_ahi : g_xhi;
    const __half* Al = mode ? g_alo : g_xlo;
    const __half* Bw = g_w16[wbase + z];

    const int gr  = tid >> 1;
    const int gs  = tid & 1;
    const size_t aoff = (size_t)(m0 + gr) * EE + gs * 16;
    const size_t boff = (size_t)(n0 + gr) * EE + gs * 16;
    const uint32_t srow = gr * ROWP + gs * 32;

    float acc[4][4][4] = {};

    auto load_tile = [&](int kt, int b) {
        const int kc = kt * 32;
        const uint32_t d = sb + b * BUFB + srow;
        cp16(d + OFF_AH,      Ah + aoff + kc);
        cp16(d + OFF_AH + 16, Ah + aoff + kc + 8);
        cp16(d + OFF_AL,      Al + aoff + kc);
        cp16(d + OFF_AL + 16, Al + aoff + kc + 8);
        cp16(d + OFF_B,       Bw + boff + kc);
        cp16(d + OFF_B + 16,  Bw + boff + kc + 8);
        asm volatile("cp.async.commit_group;" ::: "memory");
    };

    const uint32_t aBase  = (uint32_t)((wm*64 + (l & 15)) * ROWP + (l & 16));
    const uint32_t bBase4 = (uint32_t)((wn*32 + (l & 7) + ((l & 16) >> 1)) * ROWP
                                       + ((l & 8) << 1));

    load_tile(0, 0);

    for (int kt = 0; kt < NKT; kt++) {
        asm volatile("cp.async.wait_group 0;" ::: "memory");
        __syncthreads();
        if (kt + 1 < NKT) load_tile(kt + 1, (kt + 1) & 1);

        const uint32_t bufb = sb + (kt & 1) * BUFB;
        #pragma unroll
        for (int ks = 0; ks < 2; ks++) {
            const uint32_t kb = ks * 32;
            uint32_t bh[4][2], ah[4][4], al[4][4];
            LDSM_X4(bh[0][0], bh[0][1], bh[1][0], bh[1][1],
                    bufb + OFF_B + bBase4 + kb);
            LDSM_X4(bh[2][0], bh[2][1], bh[3][0], bh[3][1],
                    bufb + OFF_B + bBase4 + 16*ROWP + kb);
            #pragma unroll
            for (int mf = 0; mf < 4; mf++)
                LDSM_X4(ah[mf][0], ah[mf][1], ah[mf][2], ah[mf][3],
                        bufb + OFF_AH + aBase + mf*16*ROWP + kb);
            #pragma unroll
            for (int mf = 0; mf < 4; mf++)
                #pragma unroll
                for (int nf = 0; nf < 4; nf++)
                    MMA_F16(acc[mf][nf], ah[mf], bh[nf]);
            #pragma unroll
            for (int mf = 0; mf < 4; mf++)
                LDSM_X4(al[mf][0], al[mf][1], al[mf][2], al[mf][3],
                        bufb + OFF_AL + aBase + mf*16*ROWP + kb);
            #pragma unroll
            for (int mf = 0; mf < 4; mf++)
                #pragma unroll
                for (int nf = 0; nf < 4; nf++)
                    MMA_F16(acc[mf][nf], al[mf], bh[nf]);
        }
    }

    // Epilogue
    const int g   = l >> 2;
    const int tig = l & 3;
    #pragma unroll
    for (int mf = 0; mf < 4; mf++) {
        const int m = m0 + wm*64 + mf*16 + g;
        const int b = m >> 9;
        const int t = m & 511;
        #pragma unroll
        for (int nf = 0; nf < 4; nf++) {
            const int n = n0 + wn*32 + nf*8 + tig*2;
            float v0 = acc[mf][nf][0] + bias[n];
            float v1 = acc[mf][nf][1] + bias[n+1];
            float v2 = acc[mf][nf][2] + bias[n];
            float v3 = acc[mf][nf][3] + bias[n+1];
            if (mode == 0) {
                float* dst = z ? g_vh : g_qh;
                int h0 = n & (HH-1),   d0 = n >> 4;
                int h1 = (n+1)&(HH-1), d1 = (n+1) >> 4;
                dst[((b*HH + h0)*TT + t)*DK + d0]     = v0;
                dst[((b*HH + h1)*TT + t)*DK + d1]     = v1;
                dst[((b*HH + h0)*TT + t + 8)*DK + d0] = v2;
                dst[((b*HH + h1)*TT + t + 8)*DK + d1] = v3;
            } else {
                outp[(size_t)m*EE + n]       = v0;
                outp[(size_t)m*EE + n + 1]   = v1;
                outp[(size_t)(m+8)*EE + n]   = v2;
                outp[(size_t)(m+8)*EE + n+1] = v3;
            }
        }
    }
}

// ---------------------------------------------------------------------------
// Windowed attention, conflict-free V phase, fused fp16 split epilogue.
// grid (16, 64), 256 threads
// ---------------------------------------------------------------------------
__global__ __launch_bounds__(256) void attn_kernel()
{
    __shared__ float Ks[96][68];
    __shared__ float Ps[32][68];

    const int bh = blockIdx.y;
    const int t0 = blockIdx.x * 32;
    const float* qb = g_qh + bh*TT*DK;
    const float* vb = g_vh + bh*TT*DK;

    for (int idx = threadIdx.x; idx < 96*16; idx += 256) {
        int r  = idx >> 4;
        int c4 = (idx & 15) << 2;
        int src = t0 - 32 + r;
        src = src < 0 ? 0 : (src > TT-1 ? TT-1 : src);
        *(float4*)&Ks[r][c4] = *(const float4*)(qb + src*DK + c4);
    }
    __syncthreads();

    const int t_l = threadIdx.x >> 3;
    const int wg  = threadIdx.x & 7;
    const float scale = 1.0f / 32.0f;

    float q[64];
    const int qrow = 32 + t_l;
    #pragma unroll
    for (int i = 0; i < 16; i++) {
        float4 v = *(const float4*)&Ks[qrow][4*i];
        q[4*i] = v.x; q[4*i+1] = v.y; q[4*i+2] = v.z; q[4*i+3] = v.w;
    }

    float acc[8];
    #pragma unroll
    for (int j = 0; j < 8; j++) {
        const int r = t_l + wg + 8*j;
        float a = 0.f;
        #pragma unroll
        for (int i = 0; i < 16; i++) {
            float4 kv = *(const float4*)&Ks[r][4*i];
            a = fmaf(q[4*i],   kv.x, a);
            a = fmaf(q[4*i+1], kv.y, a);
            a = fmaf(q[4*i+2], kv.z, a);
            a = fmaf(q[4*i+3], kv.w, a);
        }
        acc[j] = a;
    }

    float m = -1e30f;
    #pragma unroll
    for (int j = 0; j < 8; j++) { acc[j] *= scale; m = fmaxf(m, acc[j]); }
    #pragma unroll
    for (int off = 1; off < 8; off <<= 1)
        m = fmaxf(m, __shfl_xor_sync(0xffffffffu, m, off));
    float s = 0.f, p[8];
    #pragma unroll
    for (int j = 0; j < 8; j++) { p[j] = __expf(acc[j] - m); s += p[j]; }
    #pragma unroll
    for (int off = 1; off < 8; off <<= 1)
        s += __shfl_xor_sync(0xffffffffu, s, off);
    float inv = 1.0f / s;
    #pragma unroll
    for (int j = 0; j < 8; j++)
        Ps[t_l][wg + 8*j] = p[j] * inv;

    __syncthreads();

    for (int idx = threadIdx.x; idx < 96*16; idx += 256) {
        int r  = idx >> 4;
        int c4 = (idx & 15) << 2;
        int src = t0 - 32 + r;
        src = src < 0 ? 0 : (src > TT-1 ? TT-1 : src);
        *(float4*)&Ks[r][c4] = *(const float4*)(vb + src*DK + c4);
    }
    __syncthreads();

    const int dg = wg;
    float ao[8] = {};
    #pragma unroll 8
    for (int w = 0; w < 64; w++) {
        float pw = Ps[t_l][w];
        const int r = t_l + w;
        float4 v0 = *(const float4*)&Ks[r][dg*4];
        float4 v1 = *(const float4*)&Ks[r][32 + dg*4];
        ao[0] = fmaf(pw, v0.x, ao[0]); ao[1] = fmaf(pw, v0.y, ao[1]);
        ao[2] = fmaf(pw, v0.z, ao[2]); ao[3] = fmaf(pw, v0.w, ao[3]);
        ao[4] = fmaf(pw, v1.x, ao[4]); ao[5] = fmaf(pw, v1.y, ao[5]);
        ao[6] = fmaf(pw, v1.z, ao[6]); ao[7] = fmaf(pw, v1.w, ao[7]);
    }

    const int b = bh >> 4, h = bh & 15;
    const int t = t0 + t_l;
    const int base = (b*TT + t)*EE + h*DK;
    __half hh[8], ll[8];
    #pragma unroll
    for (int i = 0; i < 8; i++) {
        hh[i] = __float2half(ao[i]);
        ll[i] = __float2half(ao[i] - __half2float(hh[i]));
    }
    *(uint2*)(g_ahi + base + dg*4)      = *(uint2*)(hh);
    *(uint2*)(g_ahi + base + 32 + dg*4) = *(uint2*)(hh + 4);
    *(uint2*)(g_alo + base + dg*4)      = *(uint2*)(ll);
    *(uint2*)(g_alo + base + 32 + dg*4) = *(uint2*)(ll + 4);
}

// ---------------------------------------------------------------------------
// Inputs: 0:x 1:position_mask(unused) 2:Wq 3:bq 4:Wv 5:bv 6:Wo 7:bo
// ---------------------------------------------------------------------------
extern "C" void kernel_launch(void* const* d_in, const int* in_sizes, int n_in,
                              void* d_out, int out_size)
{
    const float* x  = (const float*)d_in[0];
    const float* Wq = (const float*)d_in[2];
    const float* bq = (const float*)d_in[3];
    const float* Wv = (const float*)d_in[4];
    const float* bv = (const float*)d_in[5];
    const float* Wo = (const float*)d_in[6];
    const float* bo = (const float*)d_in[7];
    float* out = (float*)d_out;

    cudaFuncSetAttribute(mma_gemm, cudaFuncAttributeMaxDynamicSharedMemorySize, SMEM_BYTES);

    split_src<<<BT*EE/1024, 256>>>(x);
    split_w<<<dim3(32, 32, 3), dim3(32, 8)>>>(Wq, Wv, Wo);
    mma_gemm<<<dim3(8, 16, 2), 256, SMEM_BYTES>>>(0, bq, bv, nullptr, 0);
    attn_kernel<<<dim3(16, 64), 256>>>();
    mma_gemm<<<dim3(8, 16, 1), 256, SMEM_BYTES>>>(2, bo, bo, out, 1);
}

// round 12
// speedup vs baseline: 1.6505x; 1.3099x over previous
#include <cuda_runtime.h>
#include <cuda_fp16.h>
#include <cstdint>

// Problem constants
#define BB 4
#define TT 512
#define EE 1024
#define HH 16
#define DK 64
#define BT (BB*TT)          // 2048

// ---------------------------------------------------------------------------
// Device scratch
// ---------------------------------------------------------------------------
__device__ float g_qh[BB*HH*TT*DK];          // head-major qlin
__device__ float g_vh[BB*HH*TT*DK];          // head-major vlin
__device__ __half g_x16[BT*EE];              // fp16(x)
__device__ __half g_a16[BT*EE];              // fp16(attn out)
__device__ __half g_w16[3][EE*EE];           // W^T fp16: [n][k]  0=Wq 1=Wv 2=Wo

__device__ __forceinline__ uint32_t smem_u32(const void* p) {
    uint32_t a;
    asm("{ .reg .u64 t; cvta.to.shared.u64 t, %1; cvt.u32.u64 %0, t; }"
        : "=r"(a) : "l"(p));
    return a;
}

__device__ __forceinline__ void cp16(uint32_t dst, const void* src) {
    asm volatile("cp.async.cg.shared.global [%0], [%1], 16;"
                 :: "r"(dst), "l"(src) : "memory");
}

#define LDSM_X4(r0,r1,r2,r3,addr) \
    asm volatile("ldmatrix.sync.aligned.m8n8.x4.shared.b16 {%0,%1,%2,%3}, [%4];" \
                 : "=r"(r0), "=r"(r1), "=r"(r2), "=r"(r3) : "r"(addr))
#define MMA_F16(c, a, b) \
    asm volatile("mma.sync.aligned.m16n8k16.row.col.f32.f16.f16.f32 " \
                 "{%0,%1,%2,%3}, {%4,%5,%6,%7}, {%8,%9}, {%0,%1,%2,%3};" \
                 : "+f"((c)[0]), "+f"((c)[1]), "+f"((c)[2]), "+f"((c)[3]) \
                 : "r"((a)[0]), "r"((a)[1]), "r"((a)[2]), "r"((a)[3]), \
                   "r"((b)[0]), "r"((b)[1]))

// smem: 2 tiles of 128 rows x 80 B (A, B), 2-stage
#define ROWP   80
#define TILEB  (128*ROWP)            // 10240
#define OFF_A  0
#define OFF_B  (1*TILEB)
#define BUFB   (2*TILEB)             // 20480
#define SMEM_BYTES (2*BUFB)          // 40960

#define NKT 32                       // 32 K-tiles of 32 -> K = 1024

// ---------------------------------------------------------------------------
// Convert fp32 x -> fp16
// ---------------------------------------------------------------------------
__global__ __launch_bounds__(256) void split_src(const float* __restrict__ src)
{
    int i = (blockIdx.x * 256 + threadIdx.x) * 4;
    float4 v = *(const float4*)(src + i);
    __half h[4];
    h[0] = __float2half(v.x); h[1] = __float2half(v.y);
    h[2] = __float2half(v.z); h[3] = __float2half(v.w);
    *(uint2*)(g_x16 + i) = *(uint2*)h;
}

// ---------------------------------------------------------------------------
// Transpose weights to fp16: g_w16[z][n][k] = fp16(W_z[k][n])
// grid (32, 32, 3), block (32, 8)
// ---------------------------------------------------------------------------
__global__ void split_w(const float* __restrict__ Wq, const float* __restrict__ Wv,
                        const float* __restrict__ Wo)
{
    __shared__ float tile[32][33];
    const int z = blockIdx.z;
    const float* W = z == 0 ? Wq : (z == 1 ? Wv : Wo);
    const int n0 = blockIdx.x * 32;
    const int k0 = blockIdx.y * 32;
    const int tx = threadIdx.x, ty = threadIdx.y;

    #pragma unroll
    for (int i = 0; i < 4; i++)
        tile[ty + 8*i][tx] = W[(size_t)(k0 + ty + 8*i)*EE + n0 + tx];
    __syncthreads();
    #pragma unroll
    for (int i = 0; i < 4; i++) {
        int r = ty + 8*i;
        g_w16[z][(size_t)(n0 + r)*EE + k0 + tx] = __float2half(tile[tx][r]);
    }
}

// ---------------------------------------------------------------------------
// Single-pass fp16 tensor-core GEMM via mma.sync (fp32 accumulate).
// C[m,n] = sum_k fp16(A)[m,k]*fp16(W)[k,n] + bias[n]
// CTA 128x128, KT=32, 8 warps (2m x 4n), 2-stage single-sync pipeline.
// ---------------------------------------------------------------------------
__global__ __launch_bounds__(256, 2) void mma_gemm(
    int wbase, const float* __restrict__ bias0, const float* __restrict__ bias1,
    float* __restrict__ outp, int mode)
{
    extern __shared__ char smem[];
    const uint32_t sb = smem_u32(smem);
    const int tid = threadIdx.x;
    const int wid = tid >> 5;
    const int l   = tid & 31;
    const int wm  = wid & 1;
    const int wn  = wid >> 1;

    const int n0 = blockIdx.x * 128;
    const int m0 = blockIdx.y * 128;
    const int z  = blockIdx.z;
    const float* bias = z ? bias1 : bias0;

    const __half* Aa = mode ? g_a16 : g_x16;
    const __half* Bw = g_w16[wbase + z];

    const int gr  = tid >> 1;
    const int gs  = tid & 1;
    const size_t aoff = (size_t)(m0 + gr) * EE + gs * 16;
    const size_t boff = (size_t)(n0 + gr) * EE + gs * 16;
    const uint32_t srow = gr * ROWP + gs * 32;

    float acc[4][4][4] = {};

    auto load_tile = [&](int kt, int b) {
        const int kc = kt * 32;
        const uint32_t d = sb + b * BUFB + srow;
        cp16(d + OFF_A,       Aa + aoff + kc);
        cp16(d + OFF_A + 16,  Aa + aoff + kc + 8);
        cp16(d + OFF_B,       Bw + boff + kc);
        cp16(d + OFF_B + 16,  Bw + boff + kc + 8);
        asm volatile("cp.async.commit_group;" ::: "memory");
    };

    const uint32_t aBase  = (uint32_t)((wm*64 + (l & 15)) * ROWP + (l & 16));
    const uint32_t bBase4 = (uint32_t)((wn*32 + (l & 7) + ((l & 16) >> 1)) * ROWP
                                       + ((l & 8) << 1));

    load_tile(0, 0);

    for (int kt = 0; kt < NKT; kt++) {
        asm volatile("cp.async.wait_group 0;" ::: "memory");
        __syncthreads();
        if (kt + 1 < NKT) load_tile(kt + 1, (kt + 1) & 1);

        const uint32_t bufb = sb + (kt & 1) * BUFB;
        #pragma unroll
        for (int ks = 0; ks < 2; ks++) {
            const uint32_t kb = ks * 32;
            uint32_t bh[4][2], ah[4][4];
            LDSM_X4(bh[0][0], bh[0][1], bh[1][0], bh[1][1],
                    bufb + OFF_B + bBase4 + kb);
            LDSM_X4(bh[2][0], bh[2][1], bh[3][0], bh[3][1],
                    bufb + OFF_B + bBase4 + 16*ROWP + kb);
            #pragma unroll
            for (int mf = 0; mf < 4; mf++)
                LDSM_X4(ah[mf][0], ah[mf][1], ah[mf][2], ah[mf][3],
                        bufb + OFF_A + aBase + mf*16*ROWP + kb);
            #pragma unroll
            for (int mf = 0; mf < 4; mf++)
                #pragma unroll
                for (int nf = 0; nf < 4; nf++)
                    MMA_F16(acc[mf][nf], ah[mf], bh[nf]);
        }
    }

    // Epilogue
    const int g   = l >> 2;
    const int tig = l & 3;
    #pragma unroll
    for (int mf = 0; mf < 4; mf++) {
        const int m = m0 + wm*64 + mf*16 + g;
        const int b = m >> 9;
        const int t = m & 511;
        #pragma unroll
        for (int nf = 0; nf < 4; nf++) {
            const int n = n0 + wn*32 + nf*8 + tig*2;
            float v0 = acc[mf][nf][0] + bias[n];
            float v1 = acc[mf][nf][1] + bias[n+1];
            float v2 = acc[mf][nf][2] + bias[n];
            float v3 = acc[mf][nf][3] + bias[n+1];
            if (mode == 0) {
                float* dst = z ? g_vh : g_qh;
                int h0 = n & (HH-1),   d0 = n >> 4;
                int h1 = (n+1)&(HH-1), d1 = (n+1) >> 4;
                dst[((b*HH + h0)*TT + t)*DK + d0]     = v0;
                dst[((b*HH + h1)*TT + t)*DK + d1]     = v1;
                dst[((b*HH + h0)*TT + t + 8)*DK + d0] = v2;
                dst[((b*HH + h1)*TT + t + 8)*DK + d1] = v3;
            } else {
                outp[(size_t)m*EE + n]       = v0;
                outp[(size_t)m*EE + n + 1]   = v1;
                outp[(size_t)(m+8)*EE + n]   = v2;
                outp[(size_t)(m+8)*EE + n+1] = v3;
            }
        }
    }
}

// ---------------------------------------------------------------------------
// Windowed attention, conflict-free V phase, fp16 epilogue (single tensor).
// grid (16, 64), 256 threads
// ---------------------------------------------------------------------------
__global__ __launch_bounds__(256) void attn_kernel()
{
    __shared__ float Ks[96][68];
    __shared__ float Ps[32][68];

    const int bh = blockIdx.y;
    const int t0 = blockIdx.x * 32;
    const float* qb = g_qh + bh*TT*DK;
    const float* vb = g_vh + bh*TT*DK;

    for (int idx = threadIdx.x; idx < 96*16; idx += 256) {
        int r  = idx >> 4;
        int c4 = (idx & 15) << 2;
        int src = t0 - 32 + r;
        src = src < 0 ? 0 : (src > TT-1 ? TT-1 : src);
        *(float4*)&Ks[r][c4] = *(const float4*)(qb + src*DK + c4);
    }
    __syncthreads();

    const int t_l = threadIdx.x >> 3;
    const int wg  = threadIdx.x & 7;
    const float scale = 1.0f / 32.0f;

    float q[64];
    const int qrow = 32 + t_l;
    #pragma unroll
    for (int i = 0; i < 16; i++) {
        float4 v = *(const float4*)&Ks[qrow][4*i];
        q[4*i] = v.x; q[4*i+1] = v.y; q[4*i+2] = v.z; q[4*i+3] = v.w;
    }

    float acc[8];
    #pragma unroll
    for (int j = 0; j < 8; j++) {
        const int r = t_l + wg + 8*j;
        float a = 0.f;
        #pragma unroll
        for (int i = 0; i < 16; i++) {
            float4 kv = *(const float4*)&Ks[r][4*i];
            a = fmaf(q[4*i],   kv.x, a);
            a = fmaf(q[4*i+1], kv.y, a);
            a = fmaf(q[4*i+2], kv.z, a);
            a = fmaf(q[4*i+3], kv.w, a);
        }
        acc[j] = a;
    }

    float m = -1e30f;
    #pragma unroll
    for (int j = 0; j < 8; j++) { acc[j] *= scale; m = fmaxf(m, acc[j]); }
    #pragma unroll
    for (int off = 1; off < 8; off <<= 1)
        m = fmaxf(m, __shfl_xor_sync(0xffffffffu, m, off));
    float s = 0.f, p[8];
    #pragma unroll
    for (int j = 0; j < 8; j++) { p[j] = __expf(acc[j] - m); s += p[j]; }
    #pragma unroll
    for (int off = 1; off < 8; off <<= 1)
        s += __shfl_xor_sync(0xffffffffu, s, off);
    float inv = 1.0f / s;
    #pragma unroll
    for (int j = 0; j < 8; j++)
        Ps[t_l][wg + 8*j] = p[j] * inv;

    __syncthreads();

    for (int idx = threadIdx.x; idx < 96*16; idx += 256) {
        int r  = idx >> 4;
        int c4 = (idx & 15) << 2;
        int src = t0 - 32 + r;
        src = src < 0 ? 0 : (src > TT-1 ? TT-1 : src);
        *(float4*)&Ks[r][c4] = *(const float4*)(vb + src*DK + c4);
    }
    __syncthreads();

    const int dg = wg;
    float ao[8] = {};
    #pragma unroll 8
    for (int w = 0; w < 64; w++) {
        float pw = Ps[t_l][w];
        const int r = t_l + w;
        float4 v0 = *(const float4*)&Ks[r][dg*4];
        float4 v1 = *(const float4*)&Ks[r][32 + dg*4];
        ao[0] = fmaf(pw, v0.x, ao[0]); ao[1] = fmaf(pw, v0.y, ao[1]);
        ao[2] = fmaf(pw, v0.z, ao[2]); ao[3] = fmaf(pw, v0.w, ao[3]);
        ao[4] = fmaf(pw, v1.x, ao[4]); ao[5] = fmaf(pw, v1.y, ao[5]);
        ao[6] = fmaf(pw, v1.z, ao[6]); ao[7] = fmaf(pw, v1.w, ao[7]);
    }

    const int b = bh >> 4, h = bh & 15;
    const int t = t0 + t_l;
    const int base = (b*TT + t)*EE + h*DK;
    __half hh[8];
    #pragma unroll
    for (int i = 0; i < 8; i++) hh[i] = __float2half(ao[i]);
    *(uint2*)(g_a16 + base + dg*4)      = *(uint2*)(hh);
    *(uint2*)(g_a16 + base + 32 + dg*4) = *(uint2*)(hh + 4);
}

// ---------------------------------------------------------------------------
// Inputs: 0:x 1:position_mask(unused) 2:Wq 3:bq 4:Wv 5:bv 6:Wo 7:bo
// ---------------------------------------------------------------------------
extern "C" void kernel_launch(void* const* d_in, const int* in_sizes, int n_in,
                              void* d_out, int out_size)
{
    const float* x  = (const float*)d_in[0];
    const float* Wq = (const float*)d_in[2];
    const float* bq = (const float*)d_in[3];
    const float* Wv = (const float*)d_in[4];
    const float* bv = (const float*)d_in[5];
    const float* Wo = (const float*)d_in[6];
    const float* bo = (const float*)d_in[7];
    float* out = (float*)d_out;

    cudaFuncSetAttribute(mma_gemm, cudaFuncAttributeMaxDynamicSharedMemorySize, SMEM_BYTES);

    split_src<<<BT*EE/1024, 256>>>(x);
    split_w<<<dim3(32, 32, 3), dim3(32, 8)>>>(Wq, Wv, Wo);
    mma_gemm<<<dim3(8, 16, 2), 256, SMEM_BYTES>>>(0, bq, bv, nullptr, 0);
    attn_kernel<<<dim3(16, 64), 256>>>();
    mma_gemm<<<dim3(8, 16, 1), 256, SMEM_BYTES>>>(2, bo, bo, out, 1);
}